// round 10
// baseline (speedup 1.0000x reference)
#include <cuda_runtime.h>
#include <cuda_fp16.h>
#include <mma.h>
#include <cstdint>

using namespace nvcuda;

#define Bb 32
#define Nn 4096
#define Mm 512
#define Cc 256
#define KF 2080            // folded forward K (0..2048 data, padded to 65*32)
#define NH 2048            // half length for inverse rows

// ---------------------------------------------------------------------------
// Global scratch (static __device__ — no runtime allocation)
// ---------------------------------------------------------------------------
__device__ __align__(16) __half g_Acos[Mm * KF];
__device__ __align__(16) __half g_Asin[Mm * KF];
__device__ __align__(16) __half g_Vp[(size_t)Bb * KF * Cc];
__device__ __align__(16) __half g_Vm[(size_t)Bb * KF * Cc];
__device__ __align__(16) __half g_icos[NH * Mm];
__device__ __align__(16) __half g_isin[NH * Mm];
__device__ __align__(16) __half g_R16[(size_t)Mm * Cc * Cc];
__device__ __align__(16) __half g_Fre16[(size_t)Bb * Mm * Cc];
__device__ __align__(16) __half g_Fim16[(size_t)Bb * Mm * Cc];
__device__ __align__(16) __half g_Gre16[(size_t)Bb * Mm * Cc];
__device__ __align__(16) __half g_Gim16[(size_t)Bb * Mm * Cc];

// ---------------------------------------------------------------------------
__device__ __forceinline__ uint32_t s2u(const void* p) {
    uint32_t a;
    asm("{ .reg .u64 t; cvta.to.shared.u64 t, %1; cvt.u32.u64 %0, t; }"
        : "=r"(a) : "l"(p));
    return a;
}

#define CP16(dst, src) \
    asm volatile("cp.async.cg.shared.global [%0], [%1], 16;" :: "r"(dst), "l"(src))
#define CP_COMMIT() asm volatile("cp.async.commit_group;")
#define CP_WAIT3()  asm volatile("cp.async.wait_group 3;" ::: "memory")
#define CP_WAIT2()  asm volatile("cp.async.wait_group 2;" ::: "memory")
#define CP_WAIT1()  asm volatile("cp.async.wait_group 1;" ::: "memory")
#define CP_WAIT0()  asm volatile("cp.async.wait_group 0;" ::: "memory")

typedef wmma::fragment<wmma::matrix_a, 16, 16, 16, __half, wmma::row_major> FragA;
typedef wmma::fragment<wmma::matrix_b, 16, 16, 16, __half, wmma::row_major> FragB;
typedef wmma::fragment<wmma::accumulator, 16, 16, 16, float> FragC;

// ---------------------------------------------------------------------------
// Prep kernels
// ---------------------------------------------------------------------------
__global__ __launch_bounds__(256) void genA_fwd() {
    int idx = blockIdx.x * blockDim.x + threadIdx.x;
    if (idx >= Mm * KF) return;
    int m = idx / KF, k = idx - m * KF;
    int t = (int)(((long long)m * k) & (Nn - 1));
    float s, c;
    sincospif((float)t * (1.0f / 2048.0f), &s, &c);
    g_Acos[idx] = __float2half(c);
    g_Asin[idx] = __float2half(-s);
}

__global__ __launch_bounds__(256) void genA_inv() {
    int idx = blockIdx.x * blockDim.x + threadIdx.x;
    if (idx >= NH * Mm) return;
    int n = idx >> 9, m = idx & 511;
    int t = (int)(((long long)m * n) & (Nn - 1));
    float s, c;
    sincospif((float)t * (1.0f / 2048.0f), &s, &c);
    g_icos[idx] = __float2half(c);
    g_isin[idx] = __float2half(s);
}

// R fp32 -> fp16 with w_m/N folded.
__global__ __launch_bounds__(256) void pack_R(const float* __restrict__ R) {
    size_t idx4 = (size_t)blockIdx.x * blockDim.x + threadIdx.x;
    size_t base = idx4 * 4;
    if (base >= (size_t)Mm * Cc * Cc) return;
    int m = (int)(base >> 16);
    float sc = (m == 0) ? (1.0f / Nn) : (2.0f / Nn);
    float4 x = *(const float4*)(R + base);
    *(__half2*)(g_R16 + base)     = __half2{__float2half(x.x * sc), __float2half(x.y * sc)};
    *(__half2*)(g_R16 + base + 2) = __half2{__float2half(x.z * sc), __float2half(x.w * sc)};
}

// Fold v -> vp/vm fp16.  idx4 over [b][KF][256/4]
__global__ __launch_bounds__(256) void packVpVm(const float* __restrict__ v) {
    size_t idx4 = (size_t)blockIdx.x * blockDim.x + threadIdx.x;
    if (idx4 >= (size_t)Bb * KF * 64) return;
    int b = (int)(idx4 / (KF * 64));
    int rem = (int)(idx4 - (size_t)b * (KF * 64));
    int k = rem >> 6, i = (rem & 63) * 4;
    float4 vp, vm;
    if (k == 0) {
        vp = *(const float4*)(v + ((size_t)b * Nn) * Cc + i);
        vm = make_float4(0.f, 0.f, 0.f, 0.f);
    } else if (k < 2048) {
        float4 a = *(const float4*)(v + ((size_t)b * Nn + k) * Cc + i);
        float4 c = *(const float4*)(v + ((size_t)b * Nn + (Nn - k)) * Cc + i);
        vp = make_float4(a.x + c.x, a.y + c.y, a.z + c.z, a.w + c.w);
        vm = make_float4(a.x - c.x, a.y - c.y, a.z - c.z, a.w - c.w);
    } else if (k == 2048) {
        vp = *(const float4*)(v + ((size_t)b * Nn + 2048) * Cc + i);
        vm = make_float4(0.f, 0.f, 0.f, 0.f);
    } else {
        vp = make_float4(0.f, 0.f, 0.f, 0.f);
        vm = vp;
    }
    size_t base = ((size_t)b * KF + k) * Cc + i;
    *(__half2*)(g_Vp + base)     = __half2{__float2half(vp.x), __float2half(vp.y)};
    *(__half2*)(g_Vp + base + 2) = __half2{__float2half(vp.z), __float2half(vp.w)};
    *(__half2*)(g_Vm + base)     = __half2{__float2half(vm.x), __float2half(vm.y)};
    *(__half2*)(g_Vm + base + 2) = __half2{__float2half(vm.z), __float2half(vm.w)};
}

// ---------------------------------------------------------------------------
// Forward WMMA GEMM. CTA 128(m) x 256(i), 256 threads, 8 warps,
// warp tile 64x64 (acc 4x4). 4-stage cp.async.
// Stage (27136B): A[128][40] @0 (10240B), B[32][264] @10240 (16896B)
// grid: (1, 8, 32); y>=4 -> sin/vm comp.
// ---------------------------------------------------------------------------
#define STAGE 27136

__global__ __launch_bounds__(256) void fwd_gemm() {
    extern __shared__ __align__(16) char sm[];
    const uint32_t sb = s2u(sm);
    const int tid = threadIdx.x;
    const int warp = tid >> 5, lane = tid & 31;
    const int wm = warp >> 2, wn = warp & 3;   // wm: 0-1 (64 rows), wn: 0-3 (64 cols)
    const int b = blockIdx.z;
    const int y = blockIdx.y;
    const int comp = (y >= 4) ? 1 : 0;
    const int yt = comp ? (y - 4) : y;

    const __half* Ap = comp ? g_Asin : g_Acos;
    const __half* Bp = comp ? g_Vm : g_Vp;
    __half* Fout = comp ? g_Fim16 : g_Fre16;
    const int row0 = yt * 128;
    const int NCH = KF / 32;

    FragC acc[4][4];
    #pragma unroll
    for (int a = 0; a < 4; a++)
        #pragma unroll
        for (int j = 0; j < 4; j++) wmma::fill_fragment(acc[a][j], 0.0f);

    const int ar = tid >> 1, aq = tid & 1;   // A: 128 rows x 2 halves(32B)
    const int br = tid >> 3, bs = tid & 7;   // B: 32 rows x 8 segs(64B)

    auto load = [&](int stage, int k0) {
        uint32_t s0 = sb + stage * STAGE;
        size_t ga = (size_t)(row0 + ar) * KF + k0 + aq * 16;
        uint32_t ad = s0 + ar * 80 + aq * 32;
        CP16(ad,      Ap + ga);
        CP16(ad + 16, Ap + ga + 8);
        size_t gb = ((size_t)b * KF + k0 + br) * Cc + bs * 32;
        uint32_t bd = s0 + 10240 + br * 528 + bs * 64;
        CP16(bd,      Bp + gb);
        CP16(bd + 16, Bp + gb + 8);
        CP16(bd + 32, Bp + gb + 16);
        CP16(bd + 48, Bp + gb + 24);
        CP_COMMIT();
    };

    load(0, 0);
    load(1, 32);
    load(2, 64);

    int stage = 0;
    for (int c = 0; c < NCH; c++) {
        if (c + 3 < NCH) {
            int ns = stage + 3; if (ns >= 4) ns -= 4;
            load(ns, (c + 3) * 32);
            CP_WAIT3();
        } else if (c + 2 < NCH) {
            CP_WAIT2();
        } else if (c + 1 < NCH) {
            CP_WAIT1();
        } else {
            CP_WAIT0();
        }
        __syncthreads();

        const char* base = sm + stage * STAGE;
        const __half* As = (const __half*)(base);
        const __half* Bs = (const __half*)(base + 10240);

        #pragma unroll
        for (int ks = 0; ks < 2; ks++) {
            const int kk = ks * 16;
            FragB bf[4];
            #pragma unroll
            for (int j = 0; j < 4; j++)
                wmma::load_matrix_sync(bf[j], Bs + kk * 264 + wn * 64 + j * 16, 264);
            #pragma unroll
            for (int ms = 0; ms < 4; ms++) {
                FragA af;
                wmma::load_matrix_sync(af, As + (wm * 64 + ms * 16) * 40 + kk, 40);
                #pragma unroll
                for (int j = 0; j < 4; j++)
                    wmma::mma_sync(acc[ms][j], af, bf[j], acc[ms][j]);
            }
        }
        __syncthreads();
        stage++; if (stage >= 4) stage = 0;
    }

    // Epilogue: per-warp smem patch (16x68 fp32), convert to fp16, store.
    float* patch = (float*)sm + warp * 1088;   // 4352B each, 8*4352 = 34816
    #pragma unroll
    for (int ms = 0; ms < 4; ms++) {
        #pragma unroll
        for (int j = 0; j < 4; j++)
            wmma::store_matrix_sync(patch + j * 16, acc[ms][j], 68, wmma::mem_row_major);
        __syncwarp();
        int mrow = row0 + wm * 64 + ms * 16;
        #pragma unroll
        for (int rr = 0; rr < 16; rr++) {
            float x0 = patch[rr * 68 + lane * 2];
            float x1 = patch[rr * 68 + lane * 2 + 1];
            *(__half2*)(Fout + ((size_t)b * Mm + mrow + rr) * Cc + wn * 64 + lane * 2)
                = __half2{__float2half(x0), __float2half(x1)};
        }
        __syncwarp();
    }
}

// ---------------------------------------------------------------------------
// Mid WMMA: for each mode m, G[32b, 256o] = F[32b, 256i] @ R16[m] (re & im).
// 256 threads, 8 warps; warp tile 32(b) x 32(o). K=256, B pipelined 4x32.
// ---------------------------------------------------------------------------
#define MAST 16896
#define MBOFF 33792

__global__ __launch_bounds__(256) void mid_wmma() {
    extern __shared__ __align__(16) char sm[];
    const uint32_t sb = s2u(sm);
    const int tid = threadIdx.x;
    const int warp = tid >> 5, lane = tid & 31;
    const int m = blockIdx.x;

    __half* Are = (__half*)sm;
    __half* Aim = (__half*)(sm + MAST);

    #pragma unroll
    for (int it = 0; it < 8; it++) {
        int idx = tid + 256 * it;
        int plane = idx >> 10, rem = idx & 1023;
        int row = rem >> 5, seg = rem & 31;
        const __half* src = (plane ? g_Fim16 : g_Fre16)
                            + ((size_t)row * Mm + m) * Cc + seg * 8;
        uint32_t dst = sb + plane * MAST + row * 528 + seg * 16;
        CP16(dst, src);
    }
    CP_COMMIT();

    const int kr = tid >> 3, seg = tid & 7;
    auto loadB = [&](int stage, int c) {
        uint32_t s0 = sb + MBOFF + stage * MAST;
        size_t gb = ((size_t)m * Cc + c * 32 + kr) * Cc + seg * 32;
        uint32_t bd = s0 + kr * 528 + seg * 64;
        CP16(bd,      g_R16 + gb);
        CP16(bd + 16, g_R16 + gb + 8);
        CP16(bd + 32, g_R16 + gb + 16);
        CP16(bd + 48, g_R16 + gb + 24);
        CP_COMMIT();
    };

    loadB(0, 0);
    loadB(1, 1);
    loadB(2, 2);

    FragC accR[2][2], accI[2][2];
    #pragma unroll
    for (int a = 0; a < 2; a++)
        #pragma unroll
        for (int j = 0; j < 2; j++) {
            wmma::fill_fragment(accR[a][j], 0.0f);
            wmma::fill_fragment(accI[a][j], 0.0f);
        }

    int stage = 0;
    for (int c = 0; c < 8; c++) {
        if (c + 3 < 8) {
            int ns = stage + 3; if (ns >= 4) ns -= 4;
            loadB(ns, c + 3);
            CP_WAIT3();
        } else if (c + 2 < 8) {
            CP_WAIT2();
        } else if (c + 1 < 8) {
            CP_WAIT1();
        } else {
            CP_WAIT0();
        }
        __syncthreads();

        const __half* Bs = (const __half*)(sm + MBOFF + stage * MAST);
        #pragma unroll
        for (int ks = 0; ks < 2; ks++) {
            const int kk = c * 32 + ks * 16;
            FragB bf[2];
            #pragma unroll
            for (int j = 0; j < 2; j++)
                wmma::load_matrix_sync(bf[j], Bs + (ks * 16) * 264 + warp * 32 + j * 16, 264);
            #pragma unroll
            for (int ms = 0; ms < 2; ms++) {
                FragA ar_, ai_;
                wmma::load_matrix_sync(ar_, Are + ms * 16 * 264 + kk, 264);
                wmma::load_matrix_sync(ai_, Aim + ms * 16 * 264 + kk, 264);
                #pragma unroll
                for (int j = 0; j < 2; j++) {
                    wmma::mma_sync(accR[ms][j], ar_, bf[j], accR[ms][j]);
                    wmma::mma_sync(accI[ms][j], ai_, bf[j], accI[ms][j]);
                }
            }
        }
        __syncthreads();
        stage++; if (stage >= 4) stage = 0;
    }

    float* bre = (float*)(sm + MBOFF) + warp * 2560;
    float* bim = bre + 1280;
    #pragma unroll
    for (int ms = 0; ms < 2; ms++)
        #pragma unroll
        for (int j = 0; j < 2; j++) {
            wmma::store_matrix_sync(bre + ms * 16 * 40 + j * 16, accR[ms][j], 40, wmma::mem_row_major);
            wmma::store_matrix_sync(bim + ms * 16 * 40 + j * 16, accI[ms][j], 40, wmma::mem_row_major);
        }
    __syncwarp();
    #pragma unroll 4
    for (int r = 0; r < 32; r++) {
        size_t g = ((size_t)r * Mm + m) * Cc + warp * 32 + lane;
        g_Gre16[g] = __float2half(bre[r * 40 + lane]);
        g_Gim16[g] = __float2half(bim[r * 40 + lane]);
    }
}

// ---------------------------------------------------------------------------
// Inverse WMMA GEMM with fused combine. CTA 128(n) x 128(o), 256 threads.
// Warps 0-3: C = cos @ Gre.  Warps 4-7: S = sin @ Gim.  Warp tile 64x64.
// Epilogue: out[n] = v[n] + C - S;  out[N-n] = v[N-n] + C + S.
// Stage (37888B): Acos[128][40] @0, Asin @10240, BGre[32][136] @20480, BGim @29184
// 3 stages = 113664; epilogue Cbuf/Sbuf 2x128x132 fp32 = 135168 (smem size).
// grid: (2, 16, 32)
// ---------------------------------------------------------------------------
#define ISTAGE 37888

__global__ __launch_bounds__(256) void inv_gemm(const float* __restrict__ v,
                                                float* __restrict__ out) {
    extern __shared__ __align__(16) char sm[];
    const uint32_t sb = s2u(sm);
    const int tid = threadIdx.x;
    const int warp = tid >> 5;
    const int comp = warp >> 2;          // 0: C (cos,Gre)   1: S (sin,Gim)
    const int w4 = warp & 3;
    const int wm = w4 >> 1, wn = w4 & 1; // warp tile 64 rows x 64 cols
    const int colt = blockIdx.x, yt = blockIdx.y, b = blockIdx.z;
    const int row0 = yt * 128, c0 = colt * 128;
    const int NCH = Mm / 32;             // 16

    FragC acc[4][4];
    #pragma unroll
    for (int a = 0; a < 4; a++)
        #pragma unroll
        for (int j = 0; j < 4; j++) wmma::fill_fragment(acc[a][j], 0.0f);

    const int ar = tid >> 1, aq = tid & 1;   // A: 128 rows x 2 halves(32B), both planes
    const int br = tid >> 3, bs = tid & 7;   // B: 32 rows x 8 segs(32B), both planes

    auto load = [&](int stage, int k0) {
        uint32_t s0 = sb + stage * ISTAGE;
        size_t ga = (size_t)(row0 + ar) * Mm + k0 + aq * 16;
        uint32_t ad = s0 + ar * 80 + aq * 32;
        CP16(ad,             g_icos + ga);
        CP16(ad + 16,        g_icos + ga + 8);
        CP16(ad + 10240,     g_isin + ga);
        CP16(ad + 10256,     g_isin + ga + 8);
        size_t gb = ((size_t)b * Mm + k0 + br) * Cc + c0 + bs * 16;
        uint32_t bd = s0 + 20480 + br * 272 + bs * 32;
        CP16(bd,             g_Gre16 + gb);
        CP16(bd + 16,        g_Gre16 + gb + 8);
        CP16(bd + 8704,      g_Gim16 + gb);
        CP16(bd + 8720,      g_Gim16 + gb + 8);
        CP_COMMIT();
    };

    load(0, 0);
    load(1, 32);

    int stage = 0;
    for (int c = 0; c < NCH; c++) {
        if (c + 2 < NCH) {
            int ns = stage + 2; if (ns >= 3) ns -= 3;
            load(ns, (c + 2) * 32);
            CP_WAIT2();
        } else if (c + 1 < NCH) {
            CP_WAIT1();
        } else {
            CP_WAIT0();
        }
        __syncthreads();

        const char* base = sm + stage * ISTAGE;
        const __half* As = (const __half*)(base + comp * 10240);
        const __half* Bs = (const __half*)(base + 20480 + comp * 8704);

        #pragma unroll
        for (int ks = 0; ks < 2; ks++) {
            const int kk = ks * 16;
            FragB bf[4];
            #pragma unroll
            for (int j = 0; j < 4; j++)
                wmma::load_matrix_sync(bf[j], Bs + kk * 136 + wn * 64 + j * 16, 136);
            #pragma unroll
            for (int ms = 0; ms < 4; ms++) {
                FragA af;
                wmma::load_matrix_sync(af, As + (wm * 64 + ms * 16) * 40 + kk, 40);
                #pragma unroll
                for (int j = 0; j < 4; j++)
                    wmma::mma_sync(acc[ms][j], af, bf[j], acc[ms][j]);
            }
        }
        __syncthreads();
        stage++; if (stage >= 3) stage = 0;
    }

    // Epilogue: C and S to smem, then fused combine with v.
    float* Cbuf = (float*)sm;
    float* Sbuf = Cbuf + 128 * 132;
    float* buf = comp ? Sbuf : Cbuf;
    #pragma unroll
    for (int ms = 0; ms < 4; ms++)
        #pragma unroll
        for (int j = 0; j < 4; j++)
            wmma::store_matrix_sync(buf + (wm * 64 + ms * 16) * 132 + wn * 64 + j * 16,
                                    acc[ms][j], 132, wmma::mem_row_major);
    __syncthreads();

    #pragma unroll
    for (int it = 0; it < 16; it++) {
        int idx = tid + 256 * it;            // 0..4095 (128 rows x 32 float4)
        int r = idx >> 5, c4 = idx & 31;
        float4 C = *(const float4*)(Cbuf + r * 132 + c4 * 4);
        float4 S = *(const float4*)(Sbuf + r * 132 + c4 * 4);
        int n = row0 + r;
        int o = c0 + c4 * 4;
        size_t i1 = ((size_t)b * Nn + n) * Cc + o;
        float4 v1 = *(const float4*)(v + i1);
        *(float4*)(out + i1) = make_float4(v1.x + C.x - S.x, v1.y + C.y - S.y,
                                           v1.z + C.z - S.z, v1.w + C.w - S.w);
        if (n > 0) {
            size_t i2 = ((size_t)b * Nn + (Nn - n)) * Cc + o;
            float4 v2 = *(const float4*)(v + i2);
            *(float4*)(out + i2) = make_float4(v2.x + C.x + S.x, v2.y + C.y + S.y,
                                               v2.z + C.z + S.z, v2.w + C.w + S.w);
        }
    }
}

// out[b,2048,o] = v[b,2048,o] + sum_m (-1)^m * Gre'[b,m,o]   (reads fp16 Gre)
__global__ __launch_bounds__(64) void row2048(const float* __restrict__ v,
                                              float* __restrict__ out) {
    const int b = blockIdx.x;
    const int o = threadIdx.x * 4;
    float acc0 = 0.f, acc1 = 0.f, acc2 = 0.f, acc3 = 0.f;
    #pragma unroll 8
    for (int m = 0; m < Mm; m++) {
        float sgn = (m & 1) ? -1.0f : 1.0f;
        const __half* g = g_Gre16 + ((size_t)b * Mm + m) * Cc + o;
        __half2 a = *(const __half2*)(g);
        __half2 bb = *(const __half2*)(g + 2);
        acc0 += sgn * __half2float(a.x);
        acc1 += sgn * __half2float(a.y);
        acc2 += sgn * __half2float(bb.x);
        acc3 += sgn * __half2float(bb.y);
    }
    size_t idx = ((size_t)b * Nn + 2048) * Cc + o;
    float4 vv = *(const float4*)(v + idx);
    *(float4*)(out + idx) = make_float4(vv.x + acc0, vv.y + acc1,
                                        vv.z + acc2, vv.w + acc3);
}

// ---------------------------------------------------------------------------
extern "C" void kernel_launch(void* const* d_in, const int* in_sizes, int n_in,
                              void* d_out, int out_size) {
    const float* v = (const float*)d_in[0];
    const float* R = (const float*)d_in[1];
    float* out = (float*)d_out;

    const int smF = 4 * STAGE;       // 108544
    const int smMid = 115712;
    const int smInv = 135168;
    cudaFuncSetAttribute(fwd_gemm, cudaFuncAttributeMaxDynamicSharedMemorySize, smF);
    cudaFuncSetAttribute(mid_wmma, cudaFuncAttributeMaxDynamicSharedMemorySize, smMid);
    cudaFuncSetAttribute(inv_gemm, cudaFuncAttributeMaxDynamicSharedMemorySize, smInv);

    pack_R<<<(int)(((size_t)Mm * Cc * Cc / 4 + 255) / 256), 256>>>(R);
    genA_fwd<<<(Mm * KF) / 256, 256>>>();
    genA_inv<<<(NH * Mm) / 256, 256>>>();
    packVpVm<<<(int)(((size_t)Bb * KF * 64 + 255) / 256), 256>>>(v);
    fwd_gemm<<<dim3(1, 8, Bb), 256, smF>>>();
    mid_wmma<<<Mm, 256, smMid>>>();
    inv_gemm<<<dim3(2, 16, Bb), 256, smInv>>>(v, out);
    row2048<<<Bb, 64>>>(v, out);
}

// round 11
// speedup vs baseline: 1.0886x; 1.0886x over previous
#include <cuda_runtime.h>
#include <cuda_fp16.h>
#include <mma.h>
#include <cstdint>

using namespace nvcuda;

#define Bb 32
#define Nn 4096
#define Mm 512
#define Cc 256
#define KF 2080            // folded forward K (0..2048 data, padded to 65*32)
#define NH 2048            // half length for inverse rows

// ---------------------------------------------------------------------------
// Global scratch (static __device__ — no runtime allocation)
// ---------------------------------------------------------------------------
__device__ __align__(16) __half g_Acos[Mm * KF];
__device__ __align__(16) __half g_Asin[Mm * KF];
__device__ __align__(16) __half g_Vp[(size_t)Bb * KF * Cc];
__device__ __align__(16) __half g_Vm[(size_t)Bb * KF * Cc];
__device__ __align__(16) __half g_icos[NH * Mm];
__device__ __align__(16) __half g_isin[NH * Mm];
__device__ __align__(16) __half g_R16[(size_t)Mm * Cc * Cc];
__device__ __align__(16) __half g_Fre16[(size_t)Bb * Mm * Cc];
__device__ __align__(16) __half g_Fim16[(size_t)Bb * Mm * Cc];
__device__ __align__(16) __half g_Gre16[(size_t)Bb * Mm * Cc];
__device__ __align__(16) __half g_Gim16[(size_t)Bb * Mm * Cc];

// ---------------------------------------------------------------------------
__device__ __forceinline__ uint32_t s2u(const void* p) {
    uint32_t a;
    asm("{ .reg .u64 t; cvta.to.shared.u64 t, %1; cvt.u32.u64 %0, t; }"
        : "=r"(a) : "l"(p));
    return a;
}

#define CP16(dst, src) \
    asm volatile("cp.async.cg.shared.global [%0], [%1], 16;" :: "r"(dst), "l"(src))
#define CP_COMMIT() asm volatile("cp.async.commit_group;")
#define CP_WAIT3()  asm volatile("cp.async.wait_group 3;" ::: "memory")
#define CP_WAIT2()  asm volatile("cp.async.wait_group 2;" ::: "memory")
#define CP_WAIT1()  asm volatile("cp.async.wait_group 1;" ::: "memory")
#define CP_WAIT0()  asm volatile("cp.async.wait_group 0;" ::: "memory")

typedef wmma::fragment<wmma::matrix_a, 16, 16, 16, __half, wmma::row_major> FragA;
typedef wmma::fragment<wmma::matrix_b, 16, 16, 16, __half, wmma::row_major> FragB;
typedef wmma::fragment<wmma::accumulator, 16, 16, 16, float> FragC;

// ---------------------------------------------------------------------------
// Fused prep: one launch, 4 independent sub-tasks, block order permuted so
// DRAM-bound (pack_R / packVpVm) and MUFU-bound (genA_*) blocks overlap.
// Sub-grids (in virtual block id space):
//   [0, 32768)            pack_R      (Mm*Cc*Cc/4/256)
//   [32768, 36928)        genA_fwd    (Mm*KF/256 = 4160)
//   [36928, 41024)        genA_inv    (NH*Mm/256 = 4096)
//   [41024, 57664)        packVpVm    (Bb*KF*64/256 = 16640)
// ---------------------------------------------------------------------------
#define PREP_BLOCKS 57664

__global__ __launch_bounds__(256) void prep_all(const float* __restrict__ v,
                                                const float* __restrict__ R) {
    const int tid = threadIdx.x;
    // Permute block order (48611 coprime with 57664)
    unsigned u = (unsigned)(((unsigned long long)blockIdx.x * 48611ull) % PREP_BLOCKS);

    if (u < 32768u) {
        // ---- pack_R: R fp32 -> fp16 with w_m/N folded ----
        size_t idx4 = (size_t)u * 256 + tid;
        size_t base = idx4 * 4;
        int m = (int)(base >> 16);
        float sc = (m == 0) ? (1.0f / Nn) : (2.0f / Nn);
        float4 x = *(const float4*)(R + base);
        *(__half2*)(g_R16 + base)     = __half2{__float2half(x.x * sc), __float2half(x.y * sc)};
        *(__half2*)(g_R16 + base + 2) = __half2{__float2half(x.z * sc), __float2half(x.w * sc)};
    } else if (u < 36928u) {
        // ---- genA_fwd ----
        int idx = (int)(u - 32768u) * 256 + tid;
        int m = idx / KF, k = idx - m * KF;
        int t = (int)(((long long)m * k) & (Nn - 1));
        float s, c;
        sincospif((float)t * (1.0f / 2048.0f), &s, &c);
        g_Acos[idx] = __float2half(c);
        g_Asin[idx] = __float2half(-s);
    } else if (u < 41024u) {
        // ---- genA_inv ----
        int idx = (int)(u - 36928u) * 256 + tid;
        int n = idx >> 9, m = idx & 511;
        int t = (int)(((long long)m * n) & (Nn - 1));
        float s, c;
        sincospif((float)t * (1.0f / 2048.0f), &s, &c);
        g_icos[idx] = __float2half(c);
        g_isin[idx] = __float2half(s);
    } else {
        // ---- packVpVm ----
        size_t idx4 = (size_t)(u - 41024u) * 256 + tid;
        int b = (int)(idx4 / (KF * 64));
        int rem = (int)(idx4 - (size_t)b * (KF * 64));
        int k = rem >> 6, i = (rem & 63) * 4;
        float4 vp, vm;
        if (k == 0) {
            vp = *(const float4*)(v + ((size_t)b * Nn) * Cc + i);
            vm = make_float4(0.f, 0.f, 0.f, 0.f);
        } else if (k < 2048) {
            float4 a = *(const float4*)(v + ((size_t)b * Nn + k) * Cc + i);
            float4 c = *(const float4*)(v + ((size_t)b * Nn + (Nn - k)) * Cc + i);
            vp = make_float4(a.x + c.x, a.y + c.y, a.z + c.z, a.w + c.w);
            vm = make_float4(a.x - c.x, a.y - c.y, a.z - c.z, a.w - c.w);
        } else if (k == 2048) {
            vp = *(const float4*)(v + ((size_t)b * Nn + 2048) * Cc + i);
            vm = make_float4(0.f, 0.f, 0.f, 0.f);
        } else {
            vp = make_float4(0.f, 0.f, 0.f, 0.f);
            vm = vp;
        }
        size_t base = ((size_t)b * KF + k) * Cc + i;
        *(__half2*)(g_Vp + base)     = __half2{__float2half(vp.x), __float2half(vp.y)};
        *(__half2*)(g_Vp + base + 2) = __half2{__float2half(vp.z), __float2half(vp.w)};
        *(__half2*)(g_Vm + base)     = __half2{__float2half(vm.x), __float2half(vm.y)};
        *(__half2*)(g_Vm + base + 2) = __half2{__float2half(vm.z), __float2half(vm.w)};
    }
}

// ---------------------------------------------------------------------------
// Forward WMMA GEMM (round-9 proven config). CTA 128(m) x 256(i), 512 threads,
// 16 warps, warp tile 32x64. 4-stage cp.async. fp16 epilogue.
// Stage (27136B): A[128][40] @0 (10240B), B[32][264] @10240 (16896B)
// grid: (1, 8, 32); y>=4 -> sin/vm comp.
// ---------------------------------------------------------------------------
#define STAGE 27136

__global__ __launch_bounds__(512) void fwd_gemm() {
    extern __shared__ __align__(16) char sm[];
    const uint32_t sb = s2u(sm);
    const int tid = threadIdx.x;
    const int warp = tid >> 5, lane = tid & 31;
    const int wm = warp >> 2, wn = warp & 3;
    const int b = blockIdx.z;
    const int y = blockIdx.y;
    const int comp = (y >= 4) ? 1 : 0;
    const int yt = comp ? (y - 4) : y;

    const __half* Ap = comp ? g_Asin : g_Acos;
    const __half* Bp = comp ? g_Vm : g_Vp;
    __half* Fout = comp ? g_Fim16 : g_Fre16;
    const int row0 = yt * 128;
    const int NCH = KF / 32;

    FragC acc[2][4];
    #pragma unroll
    for (int a = 0; a < 2; a++)
        #pragma unroll
        for (int j = 0; j < 4; j++) wmma::fill_fragment(acc[a][j], 0.0f);

    const int ar = tid >> 2, aq = tid & 3;
    const int br = tid >> 4, bs = tid & 15;

    auto load = [&](int stage, int k0) {
        uint32_t s0 = sb + stage * STAGE;
        size_t ga = (size_t)(row0 + ar) * KF + k0 + aq * 8;
        CP16(s0 + ar * 80 + aq * 16, Ap + ga);
        size_t gb = ((size_t)b * KF + k0 + br) * Cc + bs * 8;
        uint32_t bd = s0 + 10240 + br * 528 + bs * 16;
        CP16(bd, Bp + gb);
        CP16(bd + 256, Bp + gb + 128);
        CP_COMMIT();
    };

    load(0, 0);
    load(1, 32);
    load(2, 64);

    int stage = 0;
    for (int c = 0; c < NCH; c++) {
        if (c + 3 < NCH) {
            int ns = stage + 3; if (ns >= 4) ns -= 4;
            load(ns, (c + 3) * 32);
            CP_WAIT3();
        } else if (c + 2 < NCH) {
            CP_WAIT2();
        } else if (c + 1 < NCH) {
            CP_WAIT1();
        } else {
            CP_WAIT0();
        }
        __syncthreads();

        const char* base = sm + stage * STAGE;
        const __half* As = (const __half*)(base);
        const __half* Bs = (const __half*)(base + 10240);

        #pragma unroll
        for (int ks = 0; ks < 2; ks++) {
            const int kk = ks * 16;
            FragB bf[4];
            #pragma unroll
            for (int j = 0; j < 4; j++)
                wmma::load_matrix_sync(bf[j], Bs + kk * 264 + wn * 64 + j * 16, 264);
            #pragma unroll
            for (int ms = 0; ms < 2; ms++) {
                FragA af;
                wmma::load_matrix_sync(af, As + (wm * 32 + ms * 16) * 40 + kk, 40);
                #pragma unroll
                for (int j = 0; j < 4; j++)
                    wmma::mma_sync(acc[ms][j], af, bf[j], acc[ms][j]);
            }
        }
        __syncthreads();
        stage++; if (stage >= 4) stage = 0;
    }

    // Epilogue: per-warp smem patch (16x68 fp32), convert to fp16, store.
    float* patch = (float*)sm + warp * 1088;
    #pragma unroll
    for (int ms = 0; ms < 2; ms++) {
        #pragma unroll
        for (int j = 0; j < 4; j++)
            wmma::store_matrix_sync(patch + j * 16, acc[ms][j], 68, wmma::mem_row_major);
        __syncwarp();
        int mrow = row0 + wm * 32 + ms * 16;
        #pragma unroll
        for (int rr = 0; rr < 16; rr++) {
            float x0 = patch[rr * 68 + lane * 2];
            float x1 = patch[rr * 68 + lane * 2 + 1];
            *(__half2*)(Fout + ((size_t)b * Mm + mrow + rr) * Cc + wn * 64 + lane * 2)
                = __half2{__float2half(x0), __float2half(x1)};
        }
        __syncwarp();
    }
}

// ---------------------------------------------------------------------------
// Mid WMMA: for each mode m, G[32b, 256o] = F[32b, 256i] @ R16[m] (re & im).
// 256 threads, 8 warps; warp tile 32(b) x 32(o). K=256, B pipelined 4x32.
// smem: A_re[32][264] @0 (16896), A_im @16896, B stages @33792 (+s*16896)
// Epilogue bounce OVERLAPS the A/B regions at offset 0 (dead after last MMA),
// so smem = 101376 and 2 CTAs/SM co-reside.
// ---------------------------------------------------------------------------
#define MAST 16896
#define MBOFF 33792

__global__ __launch_bounds__(256, 2) void mid_wmma() {
    extern __shared__ __align__(16) char sm[];
    const uint32_t sb = s2u(sm);
    const int tid = threadIdx.x;
    const int warp = tid >> 5, lane = tid & 31;
    const int m = blockIdx.x;

    __half* Are = (__half*)sm;
    __half* Aim = (__half*)(sm + MAST);

    #pragma unroll
    for (int it = 0; it < 8; it++) {
        int idx = tid + 256 * it;
        int plane = idx >> 10, rem = idx & 1023;
        int row = rem >> 5, seg = rem & 31;
        const __half* src = (plane ? g_Fim16 : g_Fre16)
                            + ((size_t)row * Mm + m) * Cc + seg * 8;
        uint32_t dst = sb + plane * MAST + row * 528 + seg * 16;
        CP16(dst, src);
    }
    CP_COMMIT();

    const int kr = tid >> 3, seg = tid & 7;
    auto loadB = [&](int stage, int c) {
        uint32_t s0 = sb + MBOFF + stage * MAST;
        size_t gb = ((size_t)m * Cc + c * 32 + kr) * Cc + seg * 32;
        uint32_t bd = s0 + kr * 528 + seg * 64;
        CP16(bd,      g_R16 + gb);
        CP16(bd + 16, g_R16 + gb + 8);
        CP16(bd + 32, g_R16 + gb + 16);
        CP16(bd + 48, g_R16 + gb + 24);
        CP_COMMIT();
    };

    loadB(0, 0);
    loadB(1, 1);
    loadB(2, 2);

    FragC accR[2][2], accI[2][2];
    #pragma unroll
    for (int a = 0; a < 2; a++)
        #pragma unroll
        for (int j = 0; j < 2; j++) {
            wmma::fill_fragment(accR[a][j], 0.0f);
            wmma::fill_fragment(accI[a][j], 0.0f);
        }

    int stage = 0;
    for (int c = 0; c < 8; c++) {
        if (c + 3 < 8) {
            int ns = stage + 3; if (ns >= 4) ns -= 4;
            loadB(ns, c + 3);
            CP_WAIT3();
        } else if (c + 2 < 8) {
            CP_WAIT2();
        } else if (c + 1 < 8) {
            CP_WAIT1();
        } else {
            CP_WAIT0();
        }
        __syncthreads();

        const __half* Bs = (const __half*)(sm + MBOFF + stage * MAST);
        #pragma unroll
        for (int ks = 0; ks < 2; ks++) {
            const int kk = c * 32 + ks * 16;
            FragB bf[2];
            #pragma unroll
            for (int j = 0; j < 2; j++)
                wmma::load_matrix_sync(bf[j], Bs + (ks * 16) * 264 + warp * 32 + j * 16, 264);
            #pragma unroll
            for (int ms = 0; ms < 2; ms++) {
                FragA ar_, ai_;
                wmma::load_matrix_sync(ar_, Are + ms * 16 * 264 + kk, 264);
                wmma::load_matrix_sync(ai_, Aim + ms * 16 * 264 + kk, 264);
                #pragma unroll
                for (int j = 0; j < 2; j++) {
                    wmma::mma_sync(accR[ms][j], ar_, bf[j], accR[ms][j]);
                    wmma::mma_sync(accI[ms][j], ai_, bf[j], accI[ms][j]);
                }
            }
        }
        __syncthreads();
        stage++; if (stage >= 4) stage = 0;
    }

    // Epilogue bounce at sm+0 (A/B regions dead now; all MMAs drained by the
    // __syncthreads at end of the last loop iteration).
    float* bre = (float*)sm + warp * 2560;     // 8 warps x 2560 fp32 = 81920B
    float* bim = bre + 1280;
    #pragma unroll
    for (int ms = 0; ms < 2; ms++)
        #pragma unroll
        for (int j = 0; j < 2; j++) {
            wmma::store_matrix_sync(bre + ms * 16 * 40 + j * 16, accR[ms][j], 40, wmma::mem_row_major);
            wmma::store_matrix_sync(bim + ms * 16 * 40 + j * 16, accI[ms][j], 40, wmma::mem_row_major);
        }
    __syncwarp();
    #pragma unroll 4
    for (int r = 0; r < 32; r++) {
        size_t g = ((size_t)r * Mm + m) * Cc + warp * 32 + lane;
        g_Gre16[g] = __float2half(bre[r * 40 + lane]);
        g_Gim16[g] = __float2half(bim[r * 40 + lane]);
    }
}

// ---------------------------------------------------------------------------
// Inverse WMMA GEMM with fused combine (round-9 proven config).
// CTA 128(n) x 128(o), 512 threads. Warps 0-7: C = cos@Gre, 8-15: S = sin@Gim.
// Epilogue: out[n] = v[n] + C - S;  out[N-n] = v[N-n] + C + S.
// Stage (37888B); 3 stages; epilogue Cbuf/Sbuf 2x128x132 fp32 (smem = 135168).
// grid: (2, 16, 32)
// ---------------------------------------------------------------------------
#define ISTAGE 37888

__global__ __launch_bounds__(512) void inv_gemm(const float* __restrict__ v,
                                                float* __restrict__ out) {
    extern __shared__ __align__(16) char sm[];
    const uint32_t sb = s2u(sm);
    const int tid = threadIdx.x;
    const int warp = tid >> 5;
    const int comp = warp >> 3;
    const int w8 = warp & 7;
    const int wm = w8 >> 1, wn = w8 & 1;
    const int colt = blockIdx.x, yt = blockIdx.y, b = blockIdx.z;
    const int row0 = yt * 128, c0 = colt * 128;
    const int NCH = Mm / 32;

    FragC acc[2][4];
    #pragma unroll
    for (int a = 0; a < 2; a++)
        #pragma unroll
        for (int j = 0; j < 4; j++) wmma::fill_fragment(acc[a][j], 0.0f);

    const int ar = tid >> 2, aq = tid & 3;
    const int br = tid >> 4, bs = tid & 15;

    auto load = [&](int stage, int k0) {
        uint32_t s0 = sb + stage * ISTAGE;
        size_t ga = (size_t)(row0 + ar) * Mm + k0 + aq * 8;
        uint32_t ad = s0 + ar * 80 + aq * 16;
        CP16(ad,         g_icos + ga);
        CP16(ad + 10240, g_isin + ga);
        size_t gb = ((size_t)b * Mm + k0 + br) * Cc + c0 + bs * 8;
        uint32_t bd = s0 + 20480 + br * 272 + bs * 16;
        CP16(bd,        g_Gre16 + gb);
        CP16(bd + 8704, g_Gim16 + gb);
        CP_COMMIT();
    };

    load(0, 0);
    load(1, 32);

    int stage = 0;
    for (int c = 0; c < NCH; c++) {
        if (c + 2 < NCH) {
            int ns = stage + 2; if (ns >= 3) ns -= 3;
            load(ns, (c + 2) * 32);
            CP_WAIT2();
        } else if (c + 1 < NCH) {
            CP_WAIT1();
        } else {
            CP_WAIT0();
        }
        __syncthreads();

        const char* base = sm + stage * ISTAGE;
        const __half* As = (const __half*)(base + comp * 10240);
        const __half* Bs = (const __half*)(base + 20480 + comp * 8704);

        #pragma unroll
        for (int ks = 0; ks < 2; ks++) {
            const int kk = ks * 16;
            FragB bf[4];
            #pragma unroll
            for (int j = 0; j < 4; j++)
                wmma::load_matrix_sync(bf[j], Bs + kk * 136 + wn * 64 + j * 16, 136);
            #pragma unroll
            for (int ms = 0; ms < 2; ms++) {
                FragA af;
                wmma::load_matrix_sync(af, As + (wm * 32 + ms * 16) * 40 + kk, 40);
                #pragma unroll
                for (int j = 0; j < 4; j++)
                    wmma::mma_sync(acc[ms][j], af, bf[j], acc[ms][j]);
            }
        }
        __syncthreads();
        stage++; if (stage >= 3) stage = 0;
    }

    float* Cbuf = (float*)sm;
    float* Sbuf = Cbuf + 128 * 132;
    float* buf = comp ? Sbuf : Cbuf;
    #pragma unroll
    for (int ms = 0; ms < 2; ms++)
        #pragma unroll
        for (int j = 0; j < 4; j++)
            wmma::store_matrix_sync(buf + (wm * 32 + ms * 16) * 132 + wn * 64 + j * 16,
                                    acc[ms][j], 132, wmma::mem_row_major);
    __syncthreads();

    #pragma unroll
    for (int it = 0; it < 8; it++) {
        int idx = tid + 512 * it;
        int r = idx >> 5, c4 = idx & 31;
        float4 C = *(const float4*)(Cbuf + r * 132 + c4 * 4);
        float4 S = *(const float4*)(Sbuf + r * 132 + c4 * 4);
        int n = row0 + r;
        int o = c0 + c4 * 4;
        size_t i1 = ((size_t)b * Nn + n) * Cc + o;
        float4 v1 = *(const float4*)(v + i1);
        *(float4*)(out + i1) = make_float4(v1.x + C.x - S.x, v1.y + C.y - S.y,
                                           v1.z + C.z - S.z, v1.w + C.w - S.w);
        if (n > 0) {
            size_t i2 = ((size_t)b * Nn + (Nn - n)) * Cc + o;
            float4 v2 = *(const float4*)(v + i2);
            *(float4*)(out + i2) = make_float4(v2.x + C.x + S.x, v2.y + C.y + S.y,
                                               v2.z + C.z + S.z, v2.w + C.w + S.w);
        }
    }
}

// out[b,2048,o] = v[b,2048,o] + sum_m (-1)^m * Gre'[b,m,o]   (reads fp16 Gre)
__global__ __launch_bounds__(64) void row2048(const float* __restrict__ v,
                                              float* __restrict__ out) {
    const int b = blockIdx.x;
    const int o = threadIdx.x * 4;
    float acc0 = 0.f, acc1 = 0.f, acc2 = 0.f, acc3 = 0.f;
    #pragma unroll 8
    for (int m = 0; m < Mm; m++) {
        float sgn = (m & 1) ? -1.0f : 1.0f;
        const __half* g = g_Gre16 + ((size_t)b * Mm + m) * Cc + o;
        __half2 a = *(const __half2*)(g);
        __half2 bb = *(const __half2*)(g + 2);
        acc0 += sgn * __half2float(a.x);
        acc1 += sgn * __half2float(a.y);
        acc2 += sgn * __half2float(bb.x);
        acc3 += sgn * __half2float(bb.y);
    }
    size_t idx = ((size_t)b * Nn + 2048) * Cc + o;
    float4 vv = *(const float4*)(v + idx);
    *(float4*)(out + idx) = make_float4(vv.x + acc0, vv.y + acc1,
                                        vv.z + acc2, vv.w + acc3);
}

// ---------------------------------------------------------------------------
extern "C" void kernel_launch(void* const* d_in, const int* in_sizes, int n_in,
                              void* d_out, int out_size) {
    const float* v = (const float*)d_in[0];
    const float* R = (const float*)d_in[1];
    float* out = (float*)d_out;

    const int smF = 4 * STAGE;           // 108544
    const int smMid = MBOFF + 4 * MAST;  // 101376 (bounce overlaps at offset 0)
    const int smInv = 135168;
    cudaFuncSetAttribute(fwd_gemm, cudaFuncAttributeMaxDynamicSharedMemorySize, smF);
    cudaFuncSetAttribute(mid_wmma, cudaFuncAttributeMaxDynamicSharedMemorySize, smMid);
    cudaFuncSetAttribute(inv_gemm, cudaFuncAttributeMaxDynamicSharedMemorySize, smInv);

    prep_all<<<PREP_BLOCKS, 256>>>(v, R);
    fwd_gemm<<<dim3(1, 8, Bb), 512, smF>>>();
    mid_wmma<<<Mm, 256, smMid>>>();
    inv_gemm<<<dim3(2, 16, Bb), 512, smInv>>>(v, out);
    row2048<<<Bb, 64>>>(v, out);
}